// round 8
// baseline (speedup 1.0000x reference)
#include <cuda_runtime.h>
#include <cuda_bf16.h>
#include <cstdint>

// out[64,11008] = x[64,4096] @ (Wq*scale)^T + bias
// v5: v3 skeleton (256thr, BKR=64 double-buffer, split-K 8) with warp grid
//     reshaped 2(m) x 4(n), warp = M32xN32: halves A ldmatrix crossbar traffic
//     at identical register footprint (acc 32 + B 32 regs).

#define M_DIM 64
#define K_DIM 4096
#define N_DIM 11008

#define SPLITS 8
#define KSR    512          // real k per split
#define BKR    64           // real k per stage
#define NST    (KSR / BKR)  // 8 stages per CTA
#define BKE    128          // effective k per stage (hi/lo)
#define SA     136          // smem row stride in bf16 elems (128 + 8 pad)
#define BN     128          // CTA n-tile
#define THREADS 256

__device__ __align__(16) __nv_bfloat16 g_Axl[M_DIM * 8192];          // 1 MB
__device__ float g_part[SPLITS * M_DIM * N_DIM];                     // 22.5 MB

__device__ __forceinline__ unsigned pack_bf2(__nv_bfloat16 a, __nv_bfloat16 b) {
    return (unsigned)__bfloat16_as_ushort(a) | ((unsigned)__bfloat16_as_ushort(b) << 16);
}

// ---------------------------------------------------------------------------
// Kernel 1: x[64,4096] f32 -> g_Axl[64,8192] bf16, permuted hi/lo layout.
// Per 16-real-k block j: 32 keff slots; slot(sp,b,qp,e) = sp*16 + b*8 + 2qp + e
//   real k = 16j + 4qp + 2sp + e ; b=0 -> hi(x), b=1 -> lo(x)
// ---------------------------------------------------------------------------
__global__ void convx_kernel(const float* __restrict__ x) {
    int t = blockIdx.x * blockDim.x + threadIdx.x;   // 0..16383
    int m  = t >> 8;          // 0..63
    int st = (t >> 2) & 63;   // 64-real-k super-stage
    int j  = t & 3;           // 16-real-k block

    float fx[16];
    const float4* src = (const float4*)(x + m * K_DIM + st * 64 + j * 16);
    #pragma unroll
    for (int q = 0; q < 4; ++q) ((float4*)fx)[q] = src[q];

    unsigned u[16];
    #pragma unroll
    for (int sp = 0; sp < 2; ++sp) {
        #pragma unroll
        for (int qp = 0; qp < 4; ++qp) {
            int kl = 4 * qp + 2 * sp;
            float a = fx[kl], c = fx[kl + 1];
            __nv_bfloat16 ha = __float2bfloat16_rn(a);
            __nv_bfloat16 hc = __float2bfloat16_rn(c);
            float la = a - __bfloat162float(ha);
            float lc = c - __bfloat162float(hc);
            u[sp * 8 + qp]     = pack_bf2(ha, hc);
            u[sp * 8 + 4 + qp] = pack_bf2(__float2bfloat16_rn(la), __float2bfloat16_rn(lc));
        }
    }
    uint4* dst = (uint4*)(g_Axl + m * 8192 + st * 128 + j * 32);
    #pragma unroll
    for (int q = 0; q < 4; ++q) dst[q] = ((const uint4*)u)[q];
}

// ---------------------------------------------------------------------------
// Kernel 2: split-K GEMM.  CTA: 8 warps = 2(m) x 4(n), warp = M32 x N32.
// grid (86, 8).
// ---------------------------------------------------------------------------
#define MMA16816(d, a0, a1, a2, a3, b)                                          \
    asm volatile(                                                               \
        "mma.sync.aligned.m16n8k16.row.col.f32.bf16.bf16.f32 "                  \
        "{%0,%1,%2,%3}, {%4,%5,%6,%7}, {%8,%9}, {%0,%1,%2,%3};\n"               \
        : "+f"(d[0]), "+f"(d[1]), "+f"(d[2]), "+f"(d[3])                        \
        : "r"(a0), "r"(a1), "r"(a2), "r"(a3), "r"(b), "r"(b))

__device__ __forceinline__ void issue_a(uint32_t adst0, const __nv_bfloat16* agsrc,
                                        int kt, int buf) {
    #pragma unroll
    for (int j = 0; j < 4; ++j) {
        uint32_t d = adst0 + buf * (M_DIM * SA * 2) + j * (16 * SA * 2);
        const void* s = agsrc + kt * BKE + (size_t)j * 16 * 8192;
        asm volatile("cp.async.ca.shared.global [%0], [%1], 16;\n"
                     :: "r"(d), "l"(s));
    }
}

__global__ __launch_bounds__(THREADS, 2)
void qgemm_kernel(const int* __restrict__ wq, float* __restrict__ part) {
    __shared__ __align__(16) __nv_bfloat16 As[2][M_DIM * SA];

    const int tid  = threadIdx.x;
    const int lane = tid & 31;
    const int wid  = tid >> 5;
    const int qp   = lane & 3;
    const int g    = lane >> 2;
    const int warp_m = wid & 1;     // 2 m-tiles of 32 rows
    const int warp_n = wid >> 1;    // 4 n-tiles of 32 cols
    const int bn0   = blockIdx.x * BN;
    const int split = blockIdx.y;

    uint32_t sb;
    { void* p = (void*)As;
      asm("{.reg .u64 t; cvta.to.shared.u64 t, %1; cvt.u32.u64 %0, t;}"
          : "=r"(sb) : "l"(p)); }

    // ---- A cp.async mapping: thread copies 4 x 16B per stage
    const int acol = tid & 15;            // 16B chunk within keff-128 row
    const int arow = tid >> 4;            // base row, +16 per j
    const __nv_bfloat16* agsrc = g_Axl + (size_t)arow * 8192 + split * (KSR * 2) + acol * 8;
    const uint32_t adst0 = sb + (uint32_t)((arow * SA + acol * 8) * 2);

    // ---- B pointers: frag fn row = bn0 + warp_n*32 + fn*8 + g
    const int* wg[4];
    #pragma unroll
    for (int fn = 0; fn < 4; ++fn)
        wg[fn] = wq + (size_t)(bn0 + warp_n * 32 + fn * 8 + g) * K_DIM
                    + split * KSR + 4 * qp;

    // 2-slot rolling B fragment buffer: slot = j & 1
    int4 Bh[4][2];

    // ---- prologue: A stage 0, B j0/j1 of stage 0
    issue_a(adst0, agsrc, 0, 0);
    asm volatile("cp.async.commit_group;\n");
    #pragma unroll
    for (int fn = 0; fn < 4; ++fn) {
        Bh[fn][0] = *(const int4*)(wg[fn]);        // j0
        Bh[fn][1] = *(const int4*)(wg[fn] + 16);   // j1
    }

    float acc[2][4][4];
    #pragma unroll
    for (int a = 0; a < 2; ++a)
        #pragma unroll
        for (int b = 0; b < 4; ++b)
            #pragma unroll
            for (int c = 0; c < 4; ++c) acc[a][b][c] = 0.0f;

    const uint32_t aptr = sb
        + (uint32_t)(((warp_m * 32 + (lane & 15)) * SA + (lane >> 4) * 8) * 2);

    for (int kt = 0; kt < NST; ++kt) {
        if (kt + 1 < NST) issue_a(adst0, agsrc, kt + 1, (kt + 1) & 1);
        asm volatile("cp.async.commit_group;\n");
        if (kt + 1 < NST) asm volatile("cp.async.wait_group 1;\n");
        else              asm volatile("cp.async.wait_group 0;\n");
        __syncthreads();

        const uint32_t abuf = aptr + (kt & 1) * (M_DIM * SA * 2);
        const bool pf = (kt + 1 < NST);
        const int kcur = kt * BKR, knext = (kt + 1) * BKR;

        #pragma unroll
        for (int s = 0; s < 8; ++s) {
            const int slot = (s >> 1) & 1;
            unsigned bb[4];
            #pragma unroll
            for (int fn = 0; fn < 4; ++fn) {
                int vx, vy;
                if ((s & 1) == 0) { vx = Bh[fn][slot].x; vy = Bh[fn][slot].y; }
                else              { vx = Bh[fn][slot].z; vy = Bh[fn][slot].w; }
                float f0 = (float)vx, f1 = (float)vy;
                asm("cvt.rn.bf16x2.f32 %0, %1, %2;" : "=r"(bb[fn]) : "f"(f1), "f"(f0));
            }
            // staggered refills: s=1 -> j2, s=3 -> j3, s=5 -> next j0, s=7 -> next j1
            if (s == 1) {
                #pragma unroll
                for (int fn = 0; fn < 4; ++fn)
                    Bh[fn][0] = *(const int4*)(wg[fn] + kcur + 32);
            } else if (s == 3) {
                #pragma unroll
                for (int fn = 0; fn < 4; ++fn)
                    Bh[fn][1] = *(const int4*)(wg[fn] + kcur + 48);
            } else if (s == 5 && pf) {
                #pragma unroll
                for (int fn = 0; fn < 4; ++fn)
                    Bh[fn][0] = *(const int4*)(wg[fn] + knext);
            } else if (s == 7 && pf) {
                #pragma unroll
                for (int fn = 0; fn < 4; ++fn)
                    Bh[fn][1] = *(const int4*)(wg[fn] + knext + 16);
            }
            #pragma unroll
            for (int fm = 0; fm < 2; ++fm) {
                unsigned a0, a1, a2, a3;
                asm volatile(
                    "ldmatrix.sync.aligned.m8n8.x4.shared.b16 {%0,%1,%2,%3}, [%4];\n"
                    : "=r"(a0), "=r"(a1), "=r"(a2), "=r"(a3)
                    : "r"(abuf + fm * (16 * SA * 2) + s * 32));
                MMA16816(acc[fm][0], a0, a1, a2, a3, bb[0]);
                MMA16816(acc[fm][1], a0, a1, a2, a3, bb[1]);
                MMA16816(acc[fm][2], a0, a1, a2, a3, bb[2]);
                MMA16816(acc[fm][3], a0, a1, a2, a3, bb[3]);
            }
        }
        __syncthreads();
    }

    // ---- epilogue: partials to scratch
    float* P = part + (size_t)split * (M_DIM * N_DIM);
    #pragma unroll
    for (int fm = 0; fm < 2; ++fm) {
        const int m0 = warp_m * 32 + fm * 16 + g;
        #pragma unroll
        for (int fn = 0; fn < 4; ++fn) {
            const int n = bn0 + warp_n * 32 + fn * 8 + 2 * qp;
            *(float2*)(P + (size_t)m0 * N_DIM + n) =
                make_float2(acc[fm][fn][0], acc[fm][fn][1]);
            *(float2*)(P + (size_t)(m0 + 8) * N_DIM + n) =
                make_float2(acc[fm][fn][2], acc[fm][fn][3]);
        }
    }
}

// ---------------------------------------------------------------------------
// Kernel 3: out = scale * (sum of partials) + bias     (float4 vectorized)
// ---------------------------------------------------------------------------
__global__ void reduce_kernel(const float* __restrict__ wscale,
                              const float* __restrict__ bias,
                              float* __restrict__ out) {
    const int TOT4 = M_DIM * N_DIM / 4;
    int i = blockIdx.x * blockDim.x + threadIdx.x;
    if (i >= TOT4) return;
    const float4* P = (const float4*)g_part;
    float sx = 0.0f, sy = 0.0f, sz = 0.0f, sw = 0.0f;
    #pragma unroll
    for (int s = 0; s < SPLITS; ++s) {
        float4 v = P[i + (size_t)s * TOT4];
        sx += v.x; sy += v.y; sz += v.z; sw += v.w;
    }
    const float sc = wscale[0];
    int n = (4 * i) % N_DIM;
    float4 bs = *(const float4*)(bias + n);
    ((float4*)out)[i] = make_float4(sc * sx + bs.x, sc * sy + bs.y,
                                    sc * sz + bs.z, sc * sw + bs.w);
}

extern "C" void kernel_launch(void* const* d_in, const int* in_sizes, int n_in,
                              void* d_out, int out_size) {
    const float* x      = (const float*)d_in[0];
    const int*   wq     = (const int*)  d_in[1];
    const float* wscale = (const float*)d_in[2];
    const float* bias   = (const float*)d_in[3];
    float*       out    = (float*)d_out;

    float* part;
    cudaGetSymbolAddress((void**)&part, g_part);

    convx_kernel<<<128, 128>>>(x);
    qgemm_kernel<<<dim3(N_DIM / BN, SPLITS), THREADS>>>(wq, part);
    reduce_kernel<<<(M_DIM * N_DIM / 4 + 255) / 256, 256>>>(wscale, bias, out);
}